// round 15
// baseline (speedup 1.0000x reference)
#include <cuda_runtime.h>
#include <cuda_bf16.h>
#include <stdint.h>
#include <math.h>

#define TOK 4096     // B*S
#define EMB 1024     // E
#define SEQ 2048     // S
#define BSZ 2        // B
#define NH  16       // heads
#define HD  64       // head dim

// Scratch (device globals — allocation-free per harness rules)
__device__ __nv_bfloat16 g_wthi[4 * (size_t)EMB * EMB];  // W^T hi planes q,k,v,o
__device__ __nv_bfloat16 g_wtlo[4 * (size_t)EMB * EMB];
__device__ __nv_bfloat16 g_aqh[(size_t)TOK * EMB];       // pre-split inputs [T,E]
__device__ __nv_bfloat16 g_aql[(size_t)TOK * EMB];
__device__ __nv_bfloat16 g_akh[(size_t)TOK * EMB];
__device__ __nv_bfloat16 g_akl[(size_t)TOK * EMB];
__device__ __nv_bfloat16 g_avh[(size_t)TOK * EMB];
__device__ __nv_bfloat16 g_avl[(size_t)TOK * EMB];
__device__ __nv_bfloat16 g_xh[(size_t)TOK * EMB];        // attn out hi/lo [T,E]
__device__ __nv_bfloat16 g_xl[(size_t)TOK * EMB];
__device__ __nv_bfloat16 g_qh[(size_t)TOK * EMB];        // head-split [B,H,S,D]
__device__ __nv_bfloat16 g_ql[(size_t)TOK * EMB];
__device__ __nv_bfloat16 g_kh[(size_t)TOK * EMB];
__device__ __nv_bfloat16 g_kl[(size_t)TOK * EMB];
__device__ __nv_bfloat16 g_vh[(size_t)TOK * EMB];
__device__ __nv_bfloat16 g_vl[(size_t)TOK * EMB];

// ===========================================================================
// Family-safe PTX helpers
// ===========================================================================
__device__ __forceinline__ uint32_t smem_u32(const void* p) {
    uint32_t a;
    asm("{ .reg .u64 t; cvta.to.shared.u64 t, %1; cvt.u32.u64 %0, t; }"
        : "=r"(a) : "l"(p));
    return a;
}
__device__ __forceinline__ void ldsm4(uint32_t* r, uint32_t addr) {
    asm volatile("ldmatrix.sync.aligned.m8n8.x4.shared.b16 {%0,%1,%2,%3}, [%4];"
        : "=r"(r[0]), "=r"(r[1]), "=r"(r[2]), "=r"(r[3]) : "r"(addr));
}
__device__ __forceinline__ void ldsm4t(uint32_t* r, uint32_t addr) {
    asm volatile("ldmatrix.sync.aligned.m8n8.x4.trans.shared.b16 {%0,%1,%2,%3}, [%4];"
        : "=r"(r[0]), "=r"(r[1]), "=r"(r[2]), "=r"(r[3]) : "r"(addr));
}
__device__ __forceinline__ void mma16816(float* c, const uint32_t* a, const uint32_t* b) {
    asm volatile("mma.sync.aligned.m16n8k16.row.col.f32.bf16.bf16.f32 "
        "{%0,%1,%2,%3}, {%4,%5,%6,%7}, {%8,%9}, {%0,%1,%2,%3};"
        : "+f"(c[0]), "+f"(c[1]), "+f"(c[2]), "+f"(c[3])
        : "r"(a[0]), "r"(a[1]), "r"(a[2]), "r"(a[3]), "r"(b[0]), "r"(b[1]));
}
__device__ __forceinline__ void cp16(uint32_t dst, const void* src) {
    asm volatile("cp.async.cg.shared.global [%0], [%1], 16;" :: "r"(dst), "l"(src));
}
#define CP_COMMIT() asm volatile("cp.async.commit_group;" ::: "memory")
#define CP_WAIT0()  asm volatile("cp.async.wait_group 0;" ::: "memory")
#define CP_WAIT1()  asm volatile("cp.async.wait_group 1;" ::: "memory")

__device__ __forceinline__ void split2(float x, float y, uint32_t& hi, uint32_t& lo) {
    const __nv_bfloat16 hx = __float2bfloat16_rn(x), hy = __float2bfloat16_rn(y);
    hi = ((uint32_t)__bfloat16_as_ushort(hy) << 16) | __bfloat16_as_ushort(hx);
    const __nv_bfloat16 lx = __float2bfloat16_rn(x - __bfloat162float(hx));
    const __nv_bfloat16 ly = __float2bfloat16_rn(y - __bfloat162float(hy));
    lo = ((uint32_t)__bfloat16_as_ushort(ly) << 16) | __bfloat16_as_ushort(lx);
}

// ===========================================================================
// Pre-split q,k,v inputs: fp32 [T,E] -> bf16 hi/lo planes [T,E]
// ===========================================================================
__global__ __launch_bounds__(256)
void split3(const float* __restrict__ q, const float* __restrict__ k,
            const float* __restrict__ v)
{
    const size_t i = ((size_t)blockIdx.x * 256 + threadIdx.x) * 4;
    {
        const float4 a = *(const float4*)(q + i);
        uint2 h, l;
        split2(a.x, a.y, h.x, l.x); split2(a.z, a.w, h.y, l.y);
        *(uint2*)&g_aqh[i] = h; *(uint2*)&g_aql[i] = l;
    }
    {
        const float4 a = *(const float4*)(k + i);
        uint2 h, l;
        split2(a.x, a.y, h.x, l.x); split2(a.z, a.w, h.y, l.y);
        *(uint2*)&g_akh[i] = h; *(uint2*)&g_akl[i] = l;
    }
    {
        const float4 a = *(const float4*)(v + i);
        uint2 h, l;
        split2(a.x, a.y, h.x, l.x); split2(a.z, a.w, h.y, l.y);
        *(uint2*)&g_avh[i] = h; *(uint2*)&g_avl[i] = l;
    }
}

// ===========================================================================
// All 4 weight transposes in one launch: W[k][n] fp32 -> planes[z][n][k] bf16
// ===========================================================================
__global__ __launch_bounds__(256)
void wtrans4(const float* __restrict__ wq, const float* __restrict__ wk,
             const float* __restrict__ wv, const float* __restrict__ wo)
{
    const int z = blockIdx.z;
    const float* W = (z == 0) ? wq : (z == 1) ? wk : (z == 2) ? wv : wo;
    __nv_bfloat16* WH = g_wthi + (size_t)z * EMB * EMB;
    __nv_bfloat16* WL = g_wtlo + (size_t)z * EMB * EMB;

    __shared__ float t[32][33];
    const int tx = threadIdx.x, ty = threadIdx.y;
    const int x = blockIdx.x * 32 + tx;
#pragma unroll
    for (int j = 0; j < 4; j++)
        t[ty + 8 * j][tx] = W[(size_t)(blockIdx.y * 32 + ty + 8 * j) * EMB + x];
    __syncthreads();
    const int x2 = blockIdx.y * 32 + tx;
#pragma unroll
    for (int j = 0; j < 4; j++) {
        const float f = t[tx][ty + 8 * j];
        const __nv_bfloat16 hi = __float2bfloat16_rn(f);
        const __nv_bfloat16 lo = __float2bfloat16_rn(f - __bfloat162float(hi));
        const size_t idx = (size_t)(blockIdx.x * 32 + ty + 8 * j) * EMB + x2;
        WH[idx] = hi;
        WL[idx] = lo;
    }
}

// ===========================================================================
// GEMM: 128x128 CTA tile, 8 warps (4x2), warp 32x64, BK=32, 2 CTAs/SM,
// XOR-swizzled 64B rows, 3-stage cp.async ring. (R9/R12-proven)
// ===========================================================================
#define APL  (128 * 64)                // 8192 per plane
#define STG  (4 * APL)                 // 32768 (Ahi|Alo|Bhi|Blo)
#define GEMM_SMEM (3 * STG)            // 98304

__device__ __forceinline__ void mma_chunk(float c[2][8][4], uint32_t cbs,
                                          uint32_t arowb, uint32_t acc,
                                          uint32_t browb, uint32_t bcc)
{
#pragma unroll
    for (int ks = 0; ks < 2; ks++) {
        const uint32_t ks32 = ks * 32;
        uint32_t ahi[2][4], alo[2][4], bhi[4][4], blo[4][4];
        ldsm4(ahi[0], cbs + arowb + (ks32 ^ acc));
        ldsm4(ahi[1], cbs + arowb + 1024 + (ks32 ^ acc));
        ldsm4(alo[0], cbs + APL + arowb + (ks32 ^ acc));
        ldsm4(alo[1], cbs + APL + arowb + 1024 + (ks32 ^ acc));
#pragma unroll
        for (int g = 0; g < 4; g++) {
            ldsm4(bhi[g], cbs + 2 * APL + browb + g * 1024 + (ks32 ^ bcc));
            ldsm4(blo[g], cbs + 3 * APL + browb + g * 1024 + (ks32 ^ bcc));
        }
#pragma unroll
        for (int mi = 0; mi < 2; mi++)
#pragma unroll
            for (int g = 0; g < 4; g++) {
                mma16816(c[mi][2 * g],     ahi[mi], &bhi[g][0]);
                mma16816(c[mi][2 * g + 1], ahi[mi], &bhi[g][2]);
            }
#pragma unroll
        for (int mi = 0; mi < 2; mi++)
#pragma unroll
            for (int g = 0; g < 4; g++) {
                mma16816(c[mi][2 * g],     ahi[mi], &blo[g][0]);
                mma16816(c[mi][2 * g + 1], ahi[mi], &blo[g][2]);
            }
#pragma unroll
        for (int mi = 0; mi < 2; mi++)
#pragma unroll
            for (int g = 0; g < 4; g++) {
                mma16816(c[mi][2 * g],     alo[mi], &bhi[g][0]);
                mma16816(c[mi][2 * g + 1], alo[mi], &bhi[g][2]);
            }
    }
}

__device__ __forceinline__ void stage_chunk(uint32_t st, int tid, int kk,
    const __nv_bfloat16* AH, const __nv_bfloat16* AL,
    const __nv_bfloat16* BH, const __nv_bfloat16* BL, int m0, int n0)
{
    const int row = tid >> 1, half = tid & 1;
    const uint32_t rsw = ((uint32_t)(row >> 1) & 3) << 4;
    const size_t abase = (size_t)(m0 + row) * EMB + kk;
    const size_t bbase = (size_t)(n0 + row) * EMB + kk;
    const uint32_t drow = st + (uint32_t)row * 64;
#pragma unroll
    for (int j = 0; j < 2; j++) {
        const uint32_t c = (uint32_t)(half * 2 + j);
        const uint32_t d = drow + ((c * 16) ^ rsw);
        const size_t so = c * 8;
        cp16(d,            AH + abase + so);
        cp16(d + APL,      AL + abase + so);
        cp16(d + 2 * APL,  BH + bbase + so);
        cp16(d + 3 * APL,  BL + bbase + so);
    }
}

#define GEMM_BODY(AH, AL, BH, BL)                                              \
    const int tid = threadIdx.x;                                               \
    const int lane = tid & 31;                                                 \
    const int wm = (tid >> 5) >> 1, wn = (tid >> 5) & 1;                       \
    const int m0 = blockIdx.y << 7, n0 = blockIdx.x << 7;                      \
    const uint32_t X = ((uint32_t)(lane >> 1) & 3) << 4;                       \
    const uint32_t arowb = (uint32_t)(wm * 32 + (lane & 7)                     \
                          + ((lane >> 3) & 1) * 8) * 64;                       \
    const uint32_t acc = ((uint32_t)((lane >> 4) & 1) * 16) ^ X;               \
    const uint32_t browb = (uint32_t)(wn * 64 + (lane & 7)                     \
                          + ((lane >> 4) & 1) * 8) * 64;                       \
    const uint32_t bcc = ((uint32_t)((lane >> 3) & 1) * 16) ^ X;               \
    float c[2][8][4];                                                          \
    _Pragma("unroll")                                                          \
    for (int i = 0; i < 2; i++)                                                \
        _Pragma("unroll")                                                      \
        for (int j = 0; j < 8; j++)                                            \
            _Pragma("unroll")                                                  \
            for (int u = 0; u < 4; u++) c[i][j][u] = 0.f;                      \
    stage_chunk(sbase, tid, 0, AH, AL, BH, BL, m0, n0);                        \
    CP_COMMIT();                                                               \
    stage_chunk(sbase + STG, tid, 32, AH, AL, BH, BL, m0, n0);                 \
    CP_COMMIT();                                                               \
    const int NCH = EMB / 32;                                                  \
    for (int ck = 0; ck < NCH; ck++) {                                         \
        if (ck + 1 < NCH) { CP_WAIT1(); } else { CP_WAIT0(); }                 \
        __syncthreads();                                                       \
        const uint32_t cbs = sbase + (uint32_t)(ck % 3) * STG;                 \
        mma_chunk(c, cbs, arowb, acc, browb, bcc);                             \
        if (ck + 2 < NCH) {                                                    \
            stage_chunk(sbase + (uint32_t)((ck + 2) % 3) * STG, tid,           \
                        (ck + 2) * 32, AH, AL, BH, BL, m0, n0);                \
            CP_COMMIT();                                                       \
        }                                                                      \
    }

// ===========================================================================
// Fused Q/K/V projection (z selects planes); epilogue -> head-split hi/lo.
// Q scale folds in log2(e) so attention softmax runs in exp2 domain.
// ===========================================================================
__global__ __launch_bounds__(256, 2)
void gemm_qkv(const float* __restrict__ bq, const float* __restrict__ bk,
              const float* __restrict__ bv)
{
    extern __shared__ char smem[];
    const uint32_t sbase = smem_u32(smem);
    const int z = blockIdx.z;
    const __nv_bfloat16* AH = (z == 0) ? g_aqh : (z == 1) ? g_akh : g_avh;
    const __nv_bfloat16* AL = (z == 0) ? g_aql : (z == 1) ? g_akl : g_avl;
    const __nv_bfloat16* BH = g_wthi + (size_t)z * EMB * EMB;
    const __nv_bfloat16* BL = g_wtlo + (size_t)z * EMB * EMB;
    const float* bias = (z == 0) ? bq : (z == 1) ? bk : bv;
    __nv_bfloat16* Ch = (z == 0) ? g_qh : (z == 1) ? g_kh : g_vh;
    __nv_bfloat16* Cl = (z == 0) ? g_ql : (z == 1) ? g_kl : g_vl;
    const float oscale = (z == 0) ? 0.125f * 1.44269504088896f : 1.0f;

    GEMM_BODY(AH, AL, BH, BL)

#pragma unroll
    for (int mi = 0; mi < 2; mi++) {
#pragma unroll
        for (int nf = 0; nf < 8; nf++) {
            const int n = n0 + wn * 64 + nf * 8 + (lane & 3) * 2;
            const float b0 = __ldg(&bias[n]), b1 = __ldg(&bias[n + 1]);
#pragma unroll
            for (int u2 = 0; u2 < 2; u2++) {
                const int m = m0 + wm * 32 + mi * 16 + (lane >> 2) + u2 * 8;
                const float v0 = (c[mi][nf][2 * u2]     + b0) * oscale;
                const float v1 = (c[mi][nf][2 * u2 + 1] + b1) * oscale;
                uint32_t hi, lo;
                split2(v0, v1, hi, lo);
                const int b = m >> 11, s = m & (SEQ - 1);
                const int h = n >> 6,  d = n & (HD - 1);
                const size_t idx = (((size_t)b * NH + h) * SEQ + s) * HD + d;
                *(uint32_t*)&Ch[idx] = hi;
                *(uint32_t*)&Cl[idx] = lo;
            }
        }
    }
}

// ===========================================================================
// Output projection: A = attn-out hi/lo planes, weight plane 3, fp32 out
// ===========================================================================
__global__ __launch_bounds__(256, 2)
void gemm_o(const float* __restrict__ bias, float* __restrict__ Cout)
{
    extern __shared__ char smem[];
    const uint32_t sbase = smem_u32(smem);
    const __nv_bfloat16* BH = g_wthi + 3 * (size_t)EMB * EMB;
    const __nv_bfloat16* BL = g_wtlo + 3 * (size_t)EMB * EMB;

    GEMM_BODY(g_xh, g_xl, BH, BL)

#pragma unroll
    for (int mi = 0; mi < 2; mi++) {
#pragma unroll
        for (int nf = 0; nf < 8; nf++) {
            const int n = n0 + wn * 64 + nf * 8 + (lane & 3) * 2;
            const float b0 = __ldg(&bias[n]), b1 = __ldg(&bias[n + 1]);
#pragma unroll
            for (int u2 = 0; u2 < 2; u2++) {
                const int m = m0 + wm * 32 + mi * 16 + (lane >> 2) + u2 * 8;
                Cout[(size_t)m * EMB + n]     = c[mi][nf][2 * u2]     + b0;
                Cout[(size_t)m * EMB + n + 1] = c[mi][nf][2 * u2 + 1] + b1;
            }
        }
    }
}

// ===========================================================================
// Causal flash attention, HMMA bf16x3, MAX-FREE softmax, R14 interleave,
// R15: 128-thread / 4-warp / 64-q-row CTAs, 2 independent CTAs per SM
// (no shared barrier -> phase-shifted softmax keeps tensor pipe fed).
// K 2-ring, V 3-ring, 64-key tiles.
// ===========================================================================
#define PITCH 144
#define QPL (64 * PITCH)           // 9216 per Q plane (64 q rows)
#define KPL (64 * PITCH)           // 9216 per KV plane (64 keys)
#define KST (2 * KPL)              // 18432 one KV stage (hi|lo)
#define SM_K (2 * QPL)             // 18432
#define SM_V (SM_K + 2 * KST)      // 55296
#define ATTN_SMEM (SM_V + 3 * KST) // 110592 (x2 CTAs = 221184)

__device__ __forceinline__ void issue_k(uint32_t stg,
    const __nv_bfloat16* KH, const __nv_bfloat16* KL, int k0, int tid)
{
    const int r = tid >> 1, hf = tid & 1;       // 128 threads, 2/row
    const size_t srow = (size_t)(k0 + r) * HD + hf * 32;
    const uint32_t drow = (uint32_t)r * PITCH + hf * 64;
#pragma unroll
    for (int j = 0; j < 4; j++) {
        cp16(stg + drow + 16 * j,       KH + srow + 8 * j);
        cp16(stg + KPL + drow + 16 * j, KL + srow + 8 * j);
    }
}
__device__ __forceinline__ void issue_v(uint32_t stg,
    const __nv_bfloat16* VH, const __nv_bfloat16* VL, int k0, int tid)
{
    const int r = tid >> 1, hf = tid & 1;
    const size_t srow = (size_t)(k0 + r) * HD + hf * 32;
    const uint32_t drow = (uint32_t)r * PITCH + hf * 64;
#pragma unroll
    for (int j = 0; j < 4; j++) {
        cp16(stg + drow + 16 * j,       VH + srow + 8 * j);
        cp16(stg + KPL + drow + 16 * j, VL + srow + 8 * j);
    }
}

__global__ __launch_bounds__(128, 2)
void attn_tc()
{
    extern __shared__ char smem[];
    const uint32_t sb = smem_u32(smem);
    const int tid = threadIdx.x;
    const int lane = tid & 31, w = tid >> 5;     // 4 warps
    const int qt = gridDim.x - 1 - blockIdx.x;   // longest first
    const int bh = blockIdx.y;
    const int q0 = qt << 6;                      // 64-row q tiles
    const size_t base = (size_t)bh * SEQ * HD;

    const __nv_bfloat16* KH = g_kh + base;
    const __nv_bfloat16* KL = g_kl + base;
    const __nv_bfloat16* VH = g_vh + base;
    const __nv_bfloat16* VL = g_vl + base;

    // prologue: stage Q (64 rows, both planes) + K(0) + V(0)
    {
        const int r = tid >> 1, hf = tid & 1;
        const __nv_bfloat16* sh = g_qh + base + (size_t)(q0 + r) * HD + hf * 32;
        const __nv_bfloat16* sl = g_ql + base + (size_t)(q0 + r) * HD + hf * 32;
        const uint32_t dh = sb + (uint32_t)r * PITCH + hf * 64;
#pragma unroll
        for (int j = 0; j < 4; j++) {
            cp16(dh + 16 * j, sh + 8 * j);
            cp16(dh + QPL + 16 * j, sl + 8 * j);
        }
        issue_k(sb + SM_K, KH, KL, 0, tid);
        issue_v(sb + SM_V, VH, VL, 0, tid);
        CP_COMMIT();
    }

    const uint32_t aoffQ = (uint32_t)(w * 16 + (lane & 15)) * PITCH
                         + ((lane >> 4) & 1) * 16;
    const uint32_t boff = (uint32_t)((lane & 7) + ((lane >> 4) & 1) * 8) * PITCH
                        + ((lane >> 3) & 1) * 16;
    const uint32_t voff = (uint32_t)((lane & 7) + ((lane >> 3) & 1) * 8) * PITCH
                        + ((lane >> 4) & 1) * 16;

    uint32_t qh[4][4], ql[4][4];
    uint32_t ph[4][4], pl[4][4];     // P fragments of previous tile
    float O[8][4];
#pragma unroll
    for (int nf = 0; nf < 8; nf++)
#pragma unroll
        for (int u = 0; u < 4; u++) O[nf][u] = 0.f;
    float l0 = 0.f, l1 = 0.f;

    CP_WAIT0();
    __syncthreads();
#pragma unroll
    for (int kc = 0; kc < 4; kc++) {
        ldsm4(qh[kc], sb + aoffQ + kc * 32);
        ldsm4(ql[kc], sb + QPL + aoffQ + kc * 32);
    }

    const int ktmax = qt;
    for (int kt = 0; kt <= ktmax; kt++) {
        // ---- QK(kt), pairwise-interleaved MMAs ----
        float S[8][4];
#pragma unroll
        for (int nf = 0; nf < 8; nf++)
#pragma unroll
            for (int u = 0; u < 4; u++) S[nf][u] = 0.f;
        const uint32_t kb = sb + SM_K + (uint32_t)(kt & 1) * KST + boff;
#pragma unroll
        for (int kc = 0; kc < 4; kc++) {
#pragma unroll
            for (int g = 0; g < 4; g++) {
                uint32_t kh4[4], kl4[4];
                ldsm4(kh4, kb + g * 2304 + kc * 32);
                ldsm4(kl4, kb + KPL + g * 2304 + kc * 32);
                mma16816(S[2 * g],     qh[kc], kh4);
                mma16816(S[2 * g + 1], qh[kc], kh4 + 2);
                mma16816(S[2 * g],     qh[kc], kl4);
                mma16816(S[2 * g + 1], qh[kc], kl4 + 2);
                mma16816(S[2 * g],     ql[kc], kh4);
                mma16816(S[2 * g + 1], ql[kc], kh4 + 2);
            }
        }

        // prefetch next tile while QK drains
        if (kt < ktmax) {
            issue_k(sb + SM_K + (uint32_t)((kt + 1) & 1) * KST, KH, KL,
                    (kt + 1) << 6, tid);
            issue_v(sb + SM_V + (uint32_t)((kt + 1) % 3) * KST, VH, VL,
                    (kt + 1) << 6, tid);
            CP_COMMIT();
        }

        // ---- causal mask (exp2(-1e9) -> 0) ----
        const int k0 = kt << 6;
        const int grow = q0 + w * 16 + (lane >> 2);
        if (k0 + 63 > q0 + w * 16) {
#pragma unroll
            for (int nf = 0; nf < 8; nf++) {
                const int gc = k0 + nf * 8 + (lane & 3) * 2;
                if (gc     > grow)     S[nf][0] = -1e9f;
                if (gc + 1 > grow)     S[nf][1] = -1e9f;
                if (gc     > grow + 8) S[nf][2] = -1e9f;
                if (gc + 1 > grow + 8) S[nf][3] = -1e9f;
            }
        }

        // ---- PV(kt-1) with exp2(kt), l-partials and split2(kt) folded in ----
        if (kt > 0) {
            const uint32_t vb = sb + SM_V + (uint32_t)((kt - 1) % 3) * KST + voff;
#pragma unroll
            for (int kcp = 0; kcp < 4; kcp++) {
#pragma unroll
                for (int g = 0; g < 4; g++) {
                    uint32_t vh4[4], vl4[4];
                    ldsm4t(vh4, vb + kcp * 2304 + g * 32);
                    ldsm4t(vl4, vb + KPL + kcp * 2304 + g * 32);
                    mma16816(O[2 * g],     ph[kcp], vh4);
                    mma16816(O[2 * g + 1], ph[kcp], vh4 + 2);
                    mma16816(O[2 * g],     ph[kcp], vl4);
                    mma16816(O[2 * g + 1], ph[kcp], vl4 + 2);
                    mma16816(O[2 * g],     pl[kcp], vh4);
                    mma16816(O[2 * g + 1], pl[kcp], vh4 + 2);
                    // interleaved exp2 of 2 current-tile S elements
                    const int nf = kcp * 2 + (g >> 1);
                    const int u = (g & 1) * 2;
                    S[nf][u]     = exp2f(S[nf][u]);
                    S[nf][u + 1] = exp2f(S[nf][u + 1]);
                    if (u) { l1 += S[nf][u] + S[nf][u + 1]; }
                    else   { l0 += S[nf][u] + S[nf][u + 1]; }
                }
                // S[2kcp], S[2kcp+1] fully exp2'd -> rebuild P frags now
                split2(S[2 * kcp][0],     S[2 * kcp][1],     ph[kcp][0], pl[kcp][0]);
                split2(S[2 * kcp][2],     S[2 * kcp][3],     ph[kcp][1], pl[kcp][1]);
                split2(S[2 * kcp + 1][0], S[2 * kcp + 1][1], ph[kcp][2], pl[kcp][2]);
                split2(S[2 * kcp + 1][2], S[2 * kcp + 1][3], ph[kcp][3], pl[kcp][3]);
            }
        } else {
#pragma unroll
            for (int nf = 0; nf < 8; nf++) {
                S[nf][0] = exp2f(S[nf][0]);
                S[nf][1] = exp2f(S[nf][1]);
                S[nf][2] = exp2f(S[nf][2]);
                S[nf][3] = exp2f(S[nf][3]);
                l0 += S[nf][0] + S[nf][1];
                l1 += S[nf][2] + S[nf][3];
            }
#pragma unroll
            for (int kcp = 0; kcp < 4; kcp++) {
                split2(S[2 * kcp][0],     S[2 * kcp][1],     ph[kcp][0], pl[kcp][0]);
                split2(S[2 * kcp][2],     S[2 * kcp][3],     ph[kcp][1], pl[kcp][1]);
                split2(S[2 * kcp + 1][0], S[2 * kcp + 1][1], ph[kcp][2], pl[kcp][2]);
                split2(S[2 * kcp + 1][2], S[2 * kcp + 1][3], ph[kcp][3], pl[kcp][3]);
            }
        }

        if (kt < ktmax) CP_WAIT0();
        __syncthreads();
    }

    // ---- epilogue: PV(ktmax) ----
    {
        const uint32_t vb = sb + SM_V + (uint32_t)(ktmax % 3) * KST + voff;
#pragma unroll
        for (int kcp = 0; kcp < 4; kcp++) {
#pragma unroll
            for (int g = 0; g < 4; g++) {
                uint32_t vh4[4], vl4[4];
                ldsm4t(vh4, vb + kcp * 2304 + g * 32);
                ldsm4t(vl4, vb + KPL + kcp * 2304 + g * 32);
                mma16816(O[2 * g],     ph[kcp], vh4);
                mma16816(O[2 * g + 1], ph[kcp], vh4 + 2);
                mma16816(O[2 * g],     ph[kcp], vl4);
                mma16816(O[2 * g + 1], ph[kcp], vl4 + 2);
                mma16816(O[2 * g],     pl[kcp], vh4);
                mma16816(O[2 * g + 1], pl[kcp], vh4 + 2);
            }
        }
    }

    // ---- single l reduction across the 4 lanes sharing each row ----
    l0 += __shfl_xor_sync(0xffffffffu, l0, 1);
    l0 += __shfl_xor_sync(0xffffffffu, l0, 2);
    l1 += __shfl_xor_sync(0xffffffffu, l1, 1);
    l1 += __shfl_xor_sync(0xffffffffu, l1, 2);

    // normalize + write merged-head hi/lo planes [T,E] for gemm_o
    const int b = bh >> 4, h = bh & 15;
    const float i0 = 1.f / l0, i1 = 1.f / l1;
    const int r0g = q0 + w * 16 + (lane >> 2);
#pragma unroll
    for (int nf = 0; nf < 8; nf++) {
        const int d = h * HD + nf * 8 + (lane & 3) * 2;
        uint32_t hi0, lo0, hi1, lo1;
        split2(O[nf][0] * i0, O[nf][1] * i0, hi0, lo0);
        split2(O[nf][2] * i1, O[nf][3] * i1, hi1, lo1);
        const size_t idx0 = ((size_t)b * SEQ + r0g) * EMB + d;
        const size_t idx1 = ((size_t)b * SEQ + r0g + 8) * EMB + d;
        *(uint32_t*)&g_xh[idx0] = hi0;
        *(uint32_t*)&g_xl[idx0] = lo0;
        *(uint32_t*)&g_xh[idx1] = hi1;
        *(uint32_t*)&g_xl[idx1] = lo1;
    }
}

// ---------------------------------------------------------------------------
extern "C" void kernel_launch(void* const* d_in, const int* in_sizes, int n_in,
                              void* d_out, int out_size)
{
    const float* v  = (const float*)d_in[0];
    const float* k  = (const float*)d_in[1];
    const float* q  = (const float*)d_in[2];
    const float* wq = (const float*)d_in[4];
    const float* bq = (const float*)d_in[5];
    const float* wk = (const float*)d_in[6];
    const float* bk = (const float*)d_in[7];
    const float* wv = (const float*)d_in[8];
    const float* bv = (const float*)d_in[9];
    const float* wo = (const float*)d_in[10];
    const float* bo = (const float*)d_in[11];
    float* out = (float*)d_out;

    cudaFuncSetAttribute(gemm_qkv, cudaFuncAttributeMaxDynamicSharedMemorySize, GEMM_SMEM);
    cudaFuncSetAttribute(gemm_o,   cudaFuncAttributeMaxDynamicSharedMemorySize, GEMM_SMEM);
    cudaFuncSetAttribute(attn_tc,  cudaFuncAttributeMaxDynamicSharedMemorySize, ATTN_SMEM);

    split3<<<TOK * EMB / 1024, 256>>>(q, k, v);
    wtrans4<<<dim3(EMB / 32, EMB / 32, 4), dim3(32, 8)>>>(wq, wk, wv, wo);
    gemm_qkv<<<dim3(EMB / 128, TOK / 128, 3), 256, GEMM_SMEM>>>(bq, bk, bv);
    attn_tc<<<dim3(SEQ / 64, BSZ * NH), 128, ATTN_SMEM>>>();
    gemm_o<<<dim3(EMB / 128, TOK / 128), 256, GEMM_SMEM>>>(bo, out);
}

// round 16
// speedup vs baseline: 1.0616x; 1.0616x over previous
#include <cuda_runtime.h>
#include <cuda_bf16.h>
#include <stdint.h>
#include <math.h>

#define TOK 4096     // B*S
#define EMB 1024     // E
#define SEQ 2048     // S
#define BSZ 2        // B
#define NH  16       // heads
#define HD  64       // head dim

// Scratch (device globals — allocation-free per harness rules)
__device__ __nv_bfloat16 g_wthi[4 * (size_t)EMB * EMB];  // W^T hi planes q,k,v,o
__device__ __nv_bfloat16 g_wtlo[4 * (size_t)EMB * EMB];
__device__ __nv_bfloat16 g_aqh[(size_t)TOK * EMB];       // pre-split inputs [T,E]
__device__ __nv_bfloat16 g_aql[(size_t)TOK * EMB];
__device__ __nv_bfloat16 g_akh[(size_t)TOK * EMB];
__device__ __nv_bfloat16 g_akl[(size_t)TOK * EMB];
__device__ __nv_bfloat16 g_avh[(size_t)TOK * EMB];
__device__ __nv_bfloat16 g_avl[(size_t)TOK * EMB];
__device__ __nv_bfloat16 g_xh[(size_t)TOK * EMB];        // attn out hi/lo [T,E]
__device__ __nv_bfloat16 g_xl[(size_t)TOK * EMB];
__device__ __nv_bfloat16 g_qh[(size_t)TOK * EMB];        // head-split [B,H,S,D]
__device__ __nv_bfloat16 g_ql[(size_t)TOK * EMB];
__device__ __nv_bfloat16 g_kh[(size_t)TOK * EMB];
__device__ __nv_bfloat16 g_kl[(size_t)TOK * EMB];
__device__ __nv_bfloat16 g_vh[(size_t)TOK * EMB];
__device__ __nv_bfloat16 g_vl[(size_t)TOK * EMB];

// ===========================================================================
// Family-safe PTX helpers
// ===========================================================================
__device__ __forceinline__ uint32_t smem_u32(const void* p) {
    uint32_t a;
    asm("{ .reg .u64 t; cvta.to.shared.u64 t, %1; cvt.u32.u64 %0, t; }"
        : "=r"(a) : "l"(p));
    return a;
}
__device__ __forceinline__ void ldsm4(uint32_t* r, uint32_t addr) {
    asm volatile("ldmatrix.sync.aligned.m8n8.x4.shared.b16 {%0,%1,%2,%3}, [%4];"
        : "=r"(r[0]), "=r"(r[1]), "=r"(r[2]), "=r"(r[3]) : "r"(addr));
}
__device__ __forceinline__ void ldsm4t(uint32_t* r, uint32_t addr) {
    asm volatile("ldmatrix.sync.aligned.m8n8.x4.trans.shared.b16 {%0,%1,%2,%3}, [%4];"
        : "=r"(r[0]), "=r"(r[1]), "=r"(r[2]), "=r"(r[3]) : "r"(addr));
}
__device__ __forceinline__ void mma16816(float* c, const uint32_t* a, const uint32_t* b) {
    asm volatile("mma.sync.aligned.m16n8k16.row.col.f32.bf16.bf16.f32 "
        "{%0,%1,%2,%3}, {%4,%5,%6,%7}, {%8,%9}, {%0,%1,%2,%3};"
        : "+f"(c[0]), "+f"(c[1]), "+f"(c[2]), "+f"(c[3])
        : "r"(a[0]), "r"(a[1]), "r"(a[2]), "r"(a[3]), "r"(b[0]), "r"(b[1]));
}
__device__ __forceinline__ void cp16(uint32_t dst, const void* src) {
    asm volatile("cp.async.cg.shared.global [%0], [%1], 16;" :: "r"(dst), "l"(src));
}
#define CP_COMMIT() asm volatile("cp.async.commit_group;" ::: "memory")
#define CP_WAIT0()  asm volatile("cp.async.wait_group 0;" ::: "memory")
#define CP_WAIT1()  asm volatile("cp.async.wait_group 1;" ::: "memory")

__device__ __forceinline__ void split2(float x, float y, uint32_t& hi, uint32_t& lo) {
    const __nv_bfloat16 hx = __float2bfloat16_rn(x), hy = __float2bfloat16_rn(y);
    hi = ((uint32_t)__bfloat16_as_ushort(hy) << 16) | __bfloat16_as_ushort(hx);
    const __nv_bfloat16 lx = __float2bfloat16_rn(x - __bfloat162float(hx));
    const __nv_bfloat16 ly = __float2bfloat16_rn(y - __bfloat162float(hy));
    lo = ((uint32_t)__bfloat16_as_ushort(ly) << 16) | __bfloat16_as_ushort(lx);
}

// ===========================================================================
// Fused prep: blocks [0, PREP_SPLIT) pre-split q/k/v; rest transpose+split
// the 4 weight matrices. All blocks are 256 threads.
// ===========================================================================
#define PREP_SPLIT (TOK * EMB / 1024)          // 4096 blocks for split3 part
#define WT_BLK (EMB / 32)                      // 32 tile cols per weight

__global__ __launch_bounds__(256)
void prep_all(const float* __restrict__ q, const float* __restrict__ k,
              const float* __restrict__ v,
              const float* __restrict__ wq, const float* __restrict__ wk,
              const float* __restrict__ wv, const float* __restrict__ wo)
{
    const int bid = blockIdx.x;
    if (bid < PREP_SPLIT) {
        const size_t i = ((size_t)bid * 256 + threadIdx.x) * 4;
        {
            const float4 a = *(const float4*)(q + i);
            uint2 h, l;
            split2(a.x, a.y, h.x, l.x); split2(a.z, a.w, h.y, l.y);
            *(uint2*)&g_aqh[i] = h; *(uint2*)&g_aql[i] = l;
        }
        {
            const float4 a = *(const float4*)(k + i);
            uint2 h, l;
            split2(a.x, a.y, h.x, l.x); split2(a.z, a.w, h.y, l.y);
            *(uint2*)&g_akh[i] = h; *(uint2*)&g_akl[i] = l;
        }
        {
            const float4 a = *(const float4*)(v + i);
            uint2 h, l;
            split2(a.x, a.y, h.x, l.x); split2(a.z, a.w, h.y, l.y);
            *(uint2*)&g_avh[i] = h; *(uint2*)&g_avl[i] = l;
        }
        return;
    }

    // weight transpose part: flat index -> (z, by, bx)
    const int wb = bid - PREP_SPLIT;                 // 0 .. 4*32*32-1
    const int z  = wb / (WT_BLK * WT_BLK);
    const int r  = wb % (WT_BLK * WT_BLK);
    const int by = r / WT_BLK, bx = r % WT_BLK;
    const float* W = (z == 0) ? wq : (z == 1) ? wk : (z == 2) ? wv : wo;
    __nv_bfloat16* WH = g_wthi + (size_t)z * EMB * EMB;
    __nv_bfloat16* WL = g_wtlo + (size_t)z * EMB * EMB;

    __shared__ float t[32][33];
    const int tx = threadIdx.x & 31, ty = threadIdx.x >> 5;
    const int x = bx * 32 + tx;
#pragma unroll
    for (int j = 0; j < 4; j++)
        t[ty + 8 * j][tx] = W[(size_t)(by * 32 + ty + 8 * j) * EMB + x];
    __syncthreads();
    const int x2 = by * 32 + tx;
#pragma unroll
    for (int j = 0; j < 4; j++) {
        const float f = t[tx][ty + 8 * j];
        const __nv_bfloat16 hi = __float2bfloat16_rn(f);
        const __nv_bfloat16 lo = __float2bfloat16_rn(f - __bfloat162float(hi));
        const size_t idx = (size_t)(bx * 32 + ty + 8 * j) * EMB + x2;
        WH[idx] = hi;
        WL[idx] = lo;
    }
}

// ===========================================================================
// GEMM: 128x128 CTA tile, 8 warps (4x2), warp 32x64, BK=32, 2 CTAs/SM,
// XOR-swizzled 64B rows, 3-stage cp.async ring. (R9/R12-proven)
// ===========================================================================
#define APL  (128 * 64)                // 8192 per plane
#define STG  (4 * APL)                 // 32768 (Ahi|Alo|Bhi|Blo)
#define GEMM_SMEM (3 * STG)            // 98304

__device__ __forceinline__ void mma_chunk(float c[2][8][4], uint32_t cbs,
                                          uint32_t arowb, uint32_t acc,
                                          uint32_t browb, uint32_t bcc)
{
#pragma unroll
    for (int ks = 0; ks < 2; ks++) {
        const uint32_t ks32 = ks * 32;
        uint32_t ahi[2][4], alo[2][4], bhi[4][4], blo[4][4];
        ldsm4(ahi[0], cbs + arowb + (ks32 ^ acc));
        ldsm4(ahi[1], cbs + arowb + 1024 + (ks32 ^ acc));
        ldsm4(alo[0], cbs + APL + arowb + (ks32 ^ acc));
        ldsm4(alo[1], cbs + APL + arowb + 1024 + (ks32 ^ acc));
#pragma unroll
        for (int g = 0; g < 4; g++) {
            ldsm4(bhi[g], cbs + 2 * APL + browb + g * 1024 + (ks32 ^ bcc));
            ldsm4(blo[g], cbs + 3 * APL + browb + g * 1024 + (ks32 ^ bcc));
        }
#pragma unroll
        for (int mi = 0; mi < 2; mi++)
#pragma unroll
            for (int g = 0; g < 4; g++) {
                mma16816(c[mi][2 * g],     ahi[mi], &bhi[g][0]);
                mma16816(c[mi][2 * g + 1], ahi[mi], &bhi[g][2]);
            }
#pragma unroll
        for (int mi = 0; mi < 2; mi++)
#pragma unroll
            for (int g = 0; g < 4; g++) {
                mma16816(c[mi][2 * g],     ahi[mi], &blo[g][0]);
                mma16816(c[mi][2 * g + 1], ahi[mi], &blo[g][2]);
            }
#pragma unroll
        for (int mi = 0; mi < 2; mi++)
#pragma unroll
            for (int g = 0; g < 4; g++) {
                mma16816(c[mi][2 * g],     alo[mi], &bhi[g][0]);
                mma16816(c[mi][2 * g + 1], alo[mi], &bhi[g][2]);
            }
    }
}

__device__ __forceinline__ void stage_chunk(uint32_t st, int tid, int kk,
    const __nv_bfloat16* AH, const __nv_bfloat16* AL,
    const __nv_bfloat16* BH, const __nv_bfloat16* BL, int m0, int n0)
{
    const int row = tid >> 1, half = tid & 1;
    const uint32_t rsw = ((uint32_t)(row >> 1) & 3) << 4;
    const size_t abase = (size_t)(m0 + row) * EMB + kk;
    const size_t bbase = (size_t)(n0 + row) * EMB + kk;
    const uint32_t drow = st + (uint32_t)row * 64;
#pragma unroll
    for (int j = 0; j < 2; j++) {
        const uint32_t c = (uint32_t)(half * 2 + j);
        const uint32_t d = drow + ((c * 16) ^ rsw);
        const size_t so = c * 8;
        cp16(d,            AH + abase + so);
        cp16(d + APL,      AL + abase + so);
        cp16(d + 2 * APL,  BH + bbase + so);
        cp16(d + 3 * APL,  BL + bbase + so);
    }
}

#define GEMM_BODY(AH, AL, BH, BL)                                              \
    const int tid = threadIdx.x;                                               \
    const int lane = tid & 31;                                                 \
    const int wm = (tid >> 5) >> 1, wn = (tid >> 5) & 1;                       \
    const int m0 = blockIdx.y << 7, n0 = blockIdx.x << 7;                      \
    const uint32_t X = ((uint32_t)(lane >> 1) & 3) << 4;                       \
    const uint32_t arowb = (uint32_t)(wm * 32 + (lane & 7)                     \
                          + ((lane >> 3) & 1) * 8) * 64;                       \
    const uint32_t acc = ((uint32_t)((lane >> 4) & 1) * 16) ^ X;               \
    const uint32_t browb = (uint32_t)(wn * 64 + (lane & 7)                     \
                          + ((lane >> 4) & 1) * 8) * 64;                       \
    const uint32_t bcc = ((uint32_t)((lane >> 3) & 1) * 16) ^ X;               \
    float c[2][8][4];                                                          \
    _Pragma("unroll")                                                          \
    for (int i = 0; i < 2; i++)                                                \
        _Pragma("unroll")                                                      \
        for (int j = 0; j < 8; j++)                                            \
            _Pragma("unroll")                                                  \
            for (int u = 0; u < 4; u++) c[i][j][u] = 0.f;                      \
    stage_chunk(sbase, tid, 0, AH, AL, BH, BL, m0, n0);                        \
    CP_COMMIT();                                                               \
    stage_chunk(sbase + STG, tid, 32, AH, AL, BH, BL, m0, n0);                 \
    CP_COMMIT();                                                               \
    const int NCH = EMB / 32;                                                  \
    for (int ck = 0; ck < NCH; ck++) {                                         \
        if (ck + 1 < NCH) { CP_WAIT1(); } else { CP_WAIT0(); }                 \
        __syncthreads();                                                       \
        const uint32_t cbs = sbase + (uint32_t)(ck % 3) * STG;                 \
        mma_chunk(c, cbs, arowb, acc, browb, bcc);                             \
        if (ck + 2 < NCH) {                                                    \
            stage_chunk(sbase + (uint32_t)((ck + 2) % 3) * STG, tid,           \
                        (ck + 2) * 32, AH, AL, BH, BL, m0, n0);                \
            CP_COMMIT();                                                       \
        }                                                                      \
    }

// ===========================================================================
// Fused Q/K/V projection (z selects planes); epilogue -> head-split hi/lo.
// Q scale folds in log2(e) so attention softmax runs in exp2 domain.
// ===========================================================================
__global__ __launch_bounds__(256, 2)
void gemm_qkv(const float* __restrict__ bq, const float* __restrict__ bk,
              const float* __restrict__ bv)
{
    extern __shared__ char smem[];
    const uint32_t sbase = smem_u32(smem);
    const int z = blockIdx.z;
    const __nv_bfloat16* AH = (z == 0) ? g_aqh : (z == 1) ? g_akh : g_avh;
    const __nv_bfloat16* AL = (z == 0) ? g_aql : (z == 1) ? g_akl : g_avl;
    const __nv_bfloat16* BH = g_wthi + (size_t)z * EMB * EMB;
    const __nv_bfloat16* BL = g_wtlo + (size_t)z * EMB * EMB;
    const float* bias = (z == 0) ? bq : (z == 1) ? bk : bv;
    __nv_bfloat16* Ch = (z == 0) ? g_qh : (z == 1) ? g_kh : g_vh;
    __nv_bfloat16* Cl = (z == 0) ? g_ql : (z == 1) ? g_kl : g_vl;
    const float oscale = (z == 0) ? 0.125f * 1.44269504088896f : 1.0f;

    GEMM_BODY(AH, AL, BH, BL)

#pragma unroll
    for (int mi = 0; mi < 2; mi++) {
#pragma unroll
        for (int nf = 0; nf < 8; nf++) {
            const int n = n0 + wn * 64 + nf * 8 + (lane & 3) * 2;
            const float b0 = __ldg(&bias[n]), b1 = __ldg(&bias[n + 1]);
#pragma unroll
            for (int u2 = 0; u2 < 2; u2++) {
                const int m = m0 + wm * 32 + mi * 16 + (lane >> 2) + u2 * 8;
                const float v0 = (c[mi][nf][2 * u2]     + b0) * oscale;
                const float v1 = (c[mi][nf][2 * u2 + 1] + b1) * oscale;
                uint32_t hi, lo;
                split2(v0, v1, hi, lo);
                const int b = m >> 11, s = m & (SEQ - 1);
                const int h = n >> 6,  d = n & (HD - 1);
                const size_t idx = (((size_t)b * NH + h) * SEQ + s) * HD + d;
                *(uint32_t*)&Ch[idx] = hi;
                *(uint32_t*)&Cl[idx] = lo;
            }
        }
    }
}

// ===========================================================================
// Output projection: A = attn-out hi/lo planes, weight plane 3, fp32 out
// ===========================================================================
__global__ __launch_bounds__(256, 2)
void gemm_o(const float* __restrict__ bias, float* __restrict__ Cout)
{
    extern __shared__ char smem[];
    const uint32_t sbase = smem_u32(smem);
    const __nv_bfloat16* BH = g_wthi + 3 * (size_t)EMB * EMB;
    const __nv_bfloat16* BL = g_wtlo + 3 * (size_t)EMB * EMB;

    GEMM_BODY(g_xh, g_xl, BH, BL)

#pragma unroll
    for (int mi = 0; mi < 2; mi++) {
#pragma unroll
        for (int nf = 0; nf < 8; nf++) {
            const int n = n0 + wn * 64 + nf * 8 + (lane & 3) * 2;
            const float b0 = __ldg(&bias[n]), b1 = __ldg(&bias[n + 1]);
#pragma unroll
            for (int u2 = 0; u2 < 2; u2++) {
                const int m = m0 + wm * 32 + mi * 16 + (lane >> 2) + u2 * 8;
                Cout[(size_t)m * EMB + n]     = c[mi][nf][2 * u2]     + b0;
                Cout[(size_t)m * EMB + n + 1] = c[mi][nf][2 * u2 + 1] + b1;
            }
        }
    }
}

// ===========================================================================
// Causal flash attention, HMMA bf16x3, pipelined, MAX-FREE softmax.
// R14-proven: split2 folded into PV/exp2 loop, pairwise MMA interleave.
// K 2-ring, V 3-ring, 64-key tiles, 128-q CTA, 8 warps.
// ===========================================================================
#define PITCH 144
#define QPL (128 * PITCH)          // 18432
#define KPL (64 * PITCH)           // 9216 per plane (64 keys)
#define KST (2 * KPL)              // 18432 one K stage (hi|lo)
#define SM_K (2 * QPL)             // 36864
#define SM_V (SM_K + 2 * KST)      // 73728
#define ATTN_SMEM (SM_V + 3 * KST) // 129024

__device__ __forceinline__ void issue_k(uint32_t stg,
    const __nv_bfloat16* KH, const __nv_bfloat16* KL, int k0, int tid)
{
    const int r = tid >> 2, qd = tid & 3;
    const size_t srow = (size_t)(k0 + r) * HD + qd * 16;
    const uint32_t drow = (uint32_t)r * PITCH + qd * 32;
    cp16(stg + drow,            KH + srow);
    cp16(stg + drow + 16,       KH + srow + 8);
    cp16(stg + KPL + drow,      KL + srow);
    cp16(stg + KPL + drow + 16, KL + srow + 8);
}
__device__ __forceinline__ void issue_v(uint32_t stg,
    const __nv_bfloat16* VH, const __nv_bfloat16* VL, int k0, int tid)
{
    const int r = tid >> 2, qd = tid & 3;
    const size_t srow = (size_t)(k0 + r) * HD + qd * 16;
    const uint32_t drow = (uint32_t)r * PITCH + qd * 32;
    cp16(stg + drow,            VH + srow);
    cp16(stg + drow + 16,       VH + srow + 8);
    cp16(stg + KPL + drow,      VL + srow);
    cp16(stg + KPL + drow + 16, VL + srow + 8);
}

__global__ __launch_bounds__(256)
void attn_tc()
{
    extern __shared__ char smem[];
    const uint32_t sb = smem_u32(smem);
    const int tid = threadIdx.x;
    const int lane = tid & 31, w = tid >> 5;
    const int qt = gridDim.x - 1 - blockIdx.x;   // longest first
    const int bh = blockIdx.y;
    const int q0 = qt << 7;
    const size_t base = (size_t)bh * SEQ * HD;

    const __nv_bfloat16* KH = g_kh + base;
    const __nv_bfloat16* KL = g_kl + base;
    const __nv_bfloat16* VH = g_vh + base;
    const __nv_bfloat16* VL = g_vl + base;

    // prologue: stage Q + K(0) + V(0) in one group
    {
        const int r = tid >> 1, hf = tid & 1;
        const __nv_bfloat16* sh = g_qh + base + (size_t)(q0 + r) * HD + hf * 32;
        const __nv_bfloat16* sl = g_ql + base + (size_t)(q0 + r) * HD + hf * 32;
        const uint32_t dh = sb + (uint32_t)r * PITCH + hf * 64;
#pragma unroll
        for (int j = 0; j < 4; j++) {
            cp16(dh + 16 * j, sh + 8 * j);
            cp16(dh + QPL + 16 * j, sl + 8 * j);
        }
        issue_k(sb + SM_K, KH, KL, 0, tid);
        issue_v(sb + SM_V, VH, VL, 0, tid);
        CP_COMMIT();
    }

    const uint32_t aoffQ = (uint32_t)(w * 16 + (lane & 15)) * PITCH
                         + ((lane >> 4) & 1) * 16;
    const uint32_t boff = (uint32_t)((lane & 7) + ((lane >> 4) & 1) * 8) * PITCH
                        + ((lane >> 3) & 1) * 16;
    const uint32_t voff = (uint32_t)((lane & 7) + ((lane >> 3) & 1) * 8) * PITCH
                        + ((lane >> 4) & 1) * 16;

    uint32_t qh[4][4], ql[4][4];
    uint32_t ph[4][4], pl[4][4];     // P fragments of previous tile
    float O[8][4];
#pragma unroll
    for (int nf = 0; nf < 8; nf++)
#pragma unroll
        for (int u = 0; u < 4; u++) O[nf][u] = 0.f;
    float l0 = 0.f, l1 = 0.f;

    CP_WAIT0();
    __syncthreads();
#pragma unroll
    for (int kc = 0; kc < 4; kc++) {
        ldsm4(qh[kc], sb + aoffQ + kc * 32);
        ldsm4(ql[kc], sb + QPL + aoffQ + kc * 32);
    }

    const int ktmax = 2 * qt + 1;
    for (int kt = 0; kt <= ktmax; kt++) {
        // ---- QK(kt), pairwise-interleaved MMAs ----
        float S[8][4];
#pragma unroll
        for (int nf = 0; nf < 8; nf++)
#pragma unroll
            for (int u = 0; u < 4; u++) S[nf][u] = 0.f;
        const uint32_t kb = sb + SM_K + (uint32_t)(kt & 1) * KST + boff;
#pragma unroll
        for (int kc = 0; kc < 4; kc++) {
#pragma unroll
            for (int g = 0; g < 4; g++) {
                uint32_t kh4[4], kl4[4];
                ldsm4(kh4, kb + g * 2304 + kc * 32);
                ldsm4(kl4, kb + KPL + g * 2304 + kc * 32);
                mma16816(S[2 * g],     qh[kc], kh4);
                mma16816(S[2 * g + 1], qh[kc], kh4 + 2);
                mma16816(S[2 * g],     qh[kc], kl4);
                mma16816(S[2 * g + 1], qh[kc], kl4 + 2);
                mma16816(S[2 * g],     ql[kc], kh4);
                mma16816(S[2 * g + 1], ql[kc], kh4 + 2);
            }
        }

        // prefetch next tile while QK drains
        if (kt < ktmax) {
            issue_k(sb + SM_K + (uint32_t)((kt + 1) & 1) * KST, KH, KL,
                    (kt + 1) << 6, tid);
            issue_v(sb + SM_V + (uint32_t)((kt + 1) % 3) * KST, VH, VL,
                    (kt + 1) << 6, tid);
            CP_COMMIT();
        }

        // ---- causal mask (exp2(-1e9) -> 0) ----
        const int k0 = kt << 6;
        const int grow = q0 + w * 16 + (lane >> 2);
        if (k0 + 63 > q0 + w * 16) {
#pragma unroll
            for (int nf = 0; nf < 8; nf++) {
                const int gc = k0 + nf * 8 + (lane & 3) * 2;
                if (gc     > grow)     S[nf][0] = -1e9f;
                if (gc + 1 > grow)     S[nf][1] = -1e9f;
                if (gc     > grow + 8) S[nf][2] = -1e9f;
                if (gc + 1 > grow + 8) S[nf][3] = -1e9f;
            }
        }

        // ---- PV(kt-1) with exp2(kt), l-partials and split2(kt) folded in ----
        if (kt > 0) {
            const uint32_t vb = sb + SM_V + (uint32_t)((kt - 1) % 3) * KST + voff;
#pragma unroll
            for (int kcp = 0; kcp < 4; kcp++) {
#pragma unroll
                for (int g = 0; g < 4; g++) {
                    uint32_t vh4[4], vl4[4];
                    ldsm4t(vh4, vb + kcp * 2304 + g * 32);
                    ldsm4t(vl4, vb + KPL + kcp * 2304 + g * 32);
                    mma16816(O[2 * g],     ph[kcp], vh4);
                    mma16816(O[2 * g + 1], ph[kcp], vh4 + 2);
                    mma16816(O[2 * g],     ph[kcp], vl4);
                    mma16816(O[2 * g + 1], ph[kcp], vl4 + 2);
                    mma16816(O[2 * g],     pl[kcp], vh4);
                    mma16816(O[2 * g + 1], pl[kcp], vh4 + 2);
                    // interleaved exp2 of 2 current-tile S elements
                    const int nf = kcp * 2 + (g >> 1);
                    const int u = (g & 1) * 2;
                    S[nf][u]     = exp2f(S[nf][u]);
                    S[nf][u + 1] = exp2f(S[nf][u + 1]);
                    if (u) { l1 += S[nf][u] + S[nf][u + 1]; }
                    else   { l0 += S[nf][u] + S[nf][u + 1]; }
                }
                // S[2kcp], S[2kcp+1] fully exp2'd -> rebuild P frags now
                split2(S[2 * kcp][0],     S[2 * kcp][1],     ph[kcp][0], pl[kcp][0]);
                split2(S[2 * kcp][2],     S[2 * kcp][3],     ph[kcp][1], pl[kcp][1]);
                split2(S[2 * kcp + 1][0], S[2 * kcp + 1][1], ph[kcp][2], pl[kcp][2]);
                split2(S[2 * kcp + 1][2], S[2 * kcp + 1][3], ph[kcp][3], pl[kcp][3]);
            }
        } else {
#pragma unroll
            for (int nf = 0; nf < 8; nf++) {
                S[nf][0] = exp2f(S[nf][0]);
                S[nf][1] = exp2f(S[nf][1]);
                S[nf][2] = exp2f(S[nf][2]);
                S[nf][3] = exp2f(S[nf][3]);
                l0 += S[nf][0] + S[nf][1];
                l1 += S[nf][2] + S[nf][3];
            }
#pragma unroll
            for (int kcp = 0; kcp < 4; kcp++) {
                split2(S[2 * kcp][0],     S[2 * kcp][1],     ph[kcp][0], pl[kcp][0]);
                split2(S[2 * kcp][2],     S[2 * kcp][3],     ph[kcp][1], pl[kcp][1]);
                split2(S[2 * kcp + 1][0], S[2 * kcp + 1][1], ph[kcp][2], pl[kcp][2]);
                split2(S[2 * kcp + 1][2], S[2 * kcp + 1][3], ph[kcp][3], pl[kcp][3]);
            }
        }

        if (kt < ktmax) CP_WAIT0();
        __syncthreads();
    }

    // ---- epilogue: PV(ktmax) ----
    {
        const uint32_t vb = sb + SM_V + (uint32_t)(ktmax % 3) * KST + voff;
#pragma unroll
        for (int kcp = 0; kcp < 4; kcp++) {
#pragma unroll
            for (int g = 0; g < 4; g++) {
                uint32_t vh4[4], vl4[4];
                ldsm4t(vh4, vb + kcp * 2304 + g * 32);
                ldsm4t(vl4, vb + KPL + kcp * 2304 + g * 32);
                mma16816(O[2 * g],     ph[kcp], vh4);
                mma16816(O[2 * g + 1], ph[kcp], vh4 + 2);
                mma16816(O[2 * g],     ph[kcp], vl4);
                mma16816(O[2 * g + 1], ph[kcp], vl4 + 2);
                mma16816(O[2 * g],     pl[kcp], vh4);
                mma16816(O[2 * g + 1], pl[kcp], vh4 + 2);
            }
        }
    }

    // ---- single l reduction across the 4 lanes sharing each row ----
    l0 += __shfl_xor_sync(0xffffffffu, l0, 1);
    l0 += __shfl_xor_sync(0xffffffffu, l0, 2);
    l1 += __shfl_xor_sync(0xffffffffu, l1, 1);
    l1 += __shfl_xor_sync(0xffffffffu, l1, 2);

    // normalize + write merged-head hi/lo planes [T,E] for gemm_o
    const int b = bh >> 4, h = bh & 15;
    const float i0 = 1.f / l0, i1 = 1.f / l1;
    const int r0g = q0 + w * 16 + (lane >> 2);
#pragma unroll
    for (int nf = 0; nf < 8; nf++) {
        const int d = h * HD + nf * 8 + (lane & 3) * 2;
        uint32_t hi0, lo0, hi1, lo1;
        split2(O[nf][0] * i0, O[nf][1] * i0, hi0, lo0);
        split2(O[nf][2] * i1, O[nf][3] * i1, hi1, lo1);
        const size_t idx0 = ((size_t)b * SEQ + r0g) * EMB + d;
        const size_t idx1 = ((size_t)b * SEQ + r0g + 8) * EMB + d;
        *(uint32_t*)&g_xh[idx0] = hi0;
        *(uint32_t*)&g_xl[idx0] = lo0;
        *(uint32_t*)&g_xh[idx1] = hi1;
        *(uint32_t*)&g_xl[idx1] = lo1;
    }
}

// ---------------------------------------------------------------------------
extern "C" void kernel_launch(void* const* d_in, const int* in_sizes, int n_in,
                              void* d_out, int out_size)
{
    const float* v  = (const float*)d_in[0];
    const float* k  = (const float*)d_in[1];
    const float* q  = (const float*)d_in[2];
    const float* wq = (const float*)d_in[4];
    const float* bq = (const float*)d_in[5];
    const float* wk = (const float*)d_in[6];
    const float* bk = (const float*)d_in[7];
    const float* wv = (const float*)d_in[8];
    const float* bv = (const float*)d_in[9];
    const float* wo = (const float*)d_in[10];
    const float* bo = (const float*)d_in[11];
    float* out = (float*)d_out;

    cudaFuncSetAttribute(gemm_qkv, cudaFuncAttributeMaxDynamicSharedMemorySize, GEMM_SMEM);
    cudaFuncSetAttribute(gemm_o,   cudaFuncAttributeMaxDynamicSharedMemorySize, GEMM_SMEM);
    cudaFuncSetAttribute(attn_tc,  cudaFuncAttributeMaxDynamicSharedMemorySize, ATTN_SMEM);

    prep_all<<<PREP_SPLIT + 4 * WT_BLK * WT_BLK, 256>>>(q, k, v, wq, wk, wv, wo);
    gemm_qkv<<<dim3(EMB / 128, TOK / 128, 3), 256, GEMM_SMEM>>>(bq, bk, bv);
    attn_tc<<<dim3(SEQ / 128, BSZ * NH), 256, ATTN_SMEM>>>();
    gemm_o<<<dim3(EMB / 128, TOK / 128), 256, GEMM_SMEM>>>(bo, out);
}